// round 12
// baseline (speedup 1.0000x reference)
#include <cuda_runtime.h>
#include <cuda_bf16.h>
#include <cstdint>
#include <math.h>

#define VV 25000
#define EE 300
#define KP 304
#define HH 512
#define G4 2048
#define BB 128
#define TT 512
#define NBG 4
#define NJG 32
#define BBLK 32
#define JBLK 16

// ---------------- device scratch ----------------
__device__ float g_table[(size_t)VV * G4];        // ~205 MB
// transposed packed h: [kpair][batch], value = bf16x2 (h[2k], h[2k+1])
__device__ uint32_t g_hThi[2][256 * 128];
__device__ uint32_t g_hTlo[2][256 * 128];
__device__ __nv_bfloat16 g_ehi[(size_t)VV * KP];
__device__ __nv_bfloat16 g_elo[(size_t)VV * KP];
__device__ __nv_bfloat16 g_whi[(size_t)G4 * KP];
__device__ __nv_bfloat16 g_wlo[(size_t)G4 * KP];
__device__ unsigned g_bar[8];

// LSTM SMEM: W only (stride 520) + gsb
#define WSTR 520
#define OFF_WHI 0
#define OFF_WLO (64 * WSTR)
#define OFF_GSB_BYTES (2 * 64 * WSTR * 2)          // 133120
#define SMEM_BYTES (OFF_GSB_BYTES + 4 * 32 * 64 * 4)  // 165888

// table GEMM SMEM (stride 312)
#define TSTR 312
#define T_AHI 0
#define T_ALO (64 * TSTR)
#define T_BHI (2 * 64 * TSTR)
#define T_BLO (3 * 64 * TSTR)
#define T_SMEM_BYTES (4 * 64 * TSTR * 2)

// ---------------- helpers ----------------
__device__ __forceinline__ uint32_t smem_u32(const void* p) {
  uint32_t a;
  asm("{ .reg .u64 t; cvta.to.shared.u64 t, %1; cvt.u32.u64 %0, t; }" : "=r"(a) : "l"(p));
  return a;
}
__device__ __forceinline__ void ldsm4(uint32_t& r0, uint32_t& r1, uint32_t& r2,
                                      uint32_t& r3, uint32_t addr) {
  asm volatile("ldmatrix.sync.aligned.m8n8.x4.shared.b16 {%0,%1,%2,%3}, [%4];"
               : "=r"(r0), "=r"(r1), "=r"(r2), "=r"(r3) : "r"(addr));
}
__device__ __forceinline__ void mma16816(float* c, uint32_t a0, uint32_t a1,
                                         uint32_t a2, uint32_t a3, uint32_t b0,
                                         uint32_t b1) {
  asm volatile(
      "mma.sync.aligned.m16n8k16.row.col.f32.bf16.bf16.f32 "
      "{%0,%1,%2,%3},{%4,%5,%6,%7},{%8,%9},{%0,%1,%2,%3};"
      : "+f"(c[0]), "+f"(c[1]), "+f"(c[2]), "+f"(c[3])
      : "r"(a0), "r"(a1), "r"(a2), "r"(a3), "r"(b0), "r"(b1));
}
__device__ __forceinline__ uint32_t ldcg_u32(const uint32_t* p) {
  uint32_t v;
  asm volatile("ld.global.cg.u32 %0, [%1];" : "=r"(v) : "l"(p));
  return v;
}
__device__ __forceinline__ void stcg_u32(uint32_t* p, uint32_t v) {
  asm volatile("st.global.cg.u32 [%0], %1;" :: "l"(p), "r"(v) : "memory");
}
__device__ __forceinline__ float fsig(float x) { return __fdividef(1.f, 1.f + __expf(-x)); }
__device__ __forceinline__ float ftanh(float x) {
  return __fdividef(2.f, 1.f + __expf(-2.f * x)) - 1.f;
}

// ---------------------------------------------------------------------------
// fused split of emb (VV rows) and W_ih (G4 rows) -> bf16 hi/lo padded KP=304
// ---------------------------------------------------------------------------
__global__ void conv_split_all_kernel(const float* __restrict__ emb,
                                      const float* __restrict__ W_ih) {
  const int idx = blockIdx.x * 256 + threadIdx.x;
  if (idx >= (VV + G4) * 76) return;
  const int r = idx / 76, q = idx - r * 76;
  const float* src;
  __nv_bfloat16 *hi, *lo;
  if (r < VV) {
    src = emb + (size_t)r * EE;
    hi = g_ehi + (size_t)r * KP;
    lo = g_elo + (size_t)r * KP;
  } else {
    const int rr = r - VV;
    src = W_ih + (size_t)rr * EE;
    hi = g_whi + (size_t)rr * KP;
    lo = g_wlo + (size_t)rr * KP;
  }
  float4 v = make_float4(0.f, 0.f, 0.f, 0.f);
  if (q < 75) v = *(const float4*)(src + q * 4);
  const float vv[4] = {v.x, v.y, v.z, v.w};
  __nv_bfloat16 hb[4], lb[4];
#pragma unroll
  for (int i = 0; i < 4; i++) {
    hb[i] = __float2bfloat16(vv[i]);
    lb[i] = __float2bfloat16(vv[i] - __bfloat162float(hb[i]));
  }
  *(uint2*)(hi + q * 4) = *(uint2*)hb;
  *(uint2*)(lo + q * 4) = *(uint2*)lb;
}

// ---------------------------------------------------------------------------
// table GEMM (bf16-split HMMA): table[v][g] = emb[v].W_ih[g] + bias
// ---------------------------------------------------------------------------
__global__ __launch_bounds__(256, 1) void table_mma_kernel(
    const float* __restrict__ b_ih, const float* __restrict__ b_hh) {
  extern __shared__ __align__(16) char smem[];
  __nv_bfloat16* sb = (__nv_bfloat16*)smem;
  const int m0v = blockIdx.y * 64;
  const int n0g = blockIdx.x * 64;
  const int tid = threadIdx.x;
  const int w = tid >> 5, lane = tid & 31;

  for (int i = tid; i < 2432; i += 256) {
    const int r = i / 38, u = i - r * 38;
    const int v = m0v + r;
    uint4 hv = make_uint4(0, 0, 0, 0), lv = hv;
    if (v < VV) {
      hv = *(const uint4*)(g_ehi + (size_t)v * KP + u * 8);
      lv = *(const uint4*)(g_elo + (size_t)v * KP + u * 8);
    }
    *(uint4*)(sb + T_AHI + r * TSTR + u * 8) = hv;
    *(uint4*)(sb + T_ALO + r * TSTR + u * 8) = lv;
    const int g = n0g + r;
    *(uint4*)(sb + T_BHI + r * TSTR + u * 8) =
        *(const uint4*)(g_whi + (size_t)g * KP + u * 8);
    *(uint4*)(sb + T_BLO + r * TSTR + u * 8) =
        *(const uint4*)(g_wlo + (size_t)g * KP + u * 8);
  }
  __syncthreads();

  const int mrow = (w & 1) << 5;
  const int nb = (w >> 1) << 4;
  const int sel = lane >> 3, li = lane & 7;
  const uint32_t s0 = smem_u32(sb);
  const int aoff0 = (mrow + li + ((sel & 1) << 3)) * TSTR + ((sel >> 1) << 3);
  const int aoff1 = aoff0 + 16 * TSTR;
  const int boff = (nb + li + ((sel >> 1) << 3)) * TSTR + ((sel & 1) << 3);
  const uint32_t aAhi0 = s0 + (uint32_t)(T_AHI + aoff0) * 2;
  const uint32_t aAhi1 = s0 + (uint32_t)(T_AHI + aoff1) * 2;
  const uint32_t aAlo0 = s0 + (uint32_t)(T_ALO + aoff0) * 2;
  const uint32_t aAlo1 = s0 + (uint32_t)(T_ALO + aoff1) * 2;
  const uint32_t aBhi = s0 + (uint32_t)(T_BHI + boff) * 2;
  const uint32_t aBlo = s0 + (uint32_t)(T_BLO + boff) * 2;

  float accA[4] = {0, 0, 0, 0}, accB[4] = {0, 0, 0, 0};
  float accC[4] = {0, 0, 0, 0}, accD[4] = {0, 0, 0, 0};
#pragma unroll
  for (int ks = 0; ks < 19; ks++) {
    const uint32_t kb = (uint32_t)ks * 32;
    uint32_t h0, h1, h2, h3, l0, l1, l2, l3, p0, p1, p2, p3, q0, q1, q2, q3;
    ldsm4(p0, p1, p2, p3, aBhi + kb);
    ldsm4(q0, q1, q2, q3, aBlo + kb);
    ldsm4(h0, h1, h2, h3, aAhi0 + kb);
    ldsm4(l0, l1, l2, l3, aAlo0 + kb);
    mma16816(accA, h0, h1, h2, h3, p0, p1);
    mma16816(accB, h0, h1, h2, h3, p2, p3);
    mma16816(accA, h0, h1, h2, h3, q0, q1);
    mma16816(accB, h0, h1, h2, h3, q2, q3);
    mma16816(accA, l0, l1, l2, l3, p0, p1);
    mma16816(accB, l0, l1, l2, l3, p2, p3);
    ldsm4(h0, h1, h2, h3, aAhi1 + kb);
    ldsm4(l0, l1, l2, l3, aAlo1 + kb);
    mma16816(accC, h0, h1, h2, h3, p0, p1);
    mma16816(accD, h0, h1, h2, h3, p2, p3);
    mma16816(accC, h0, h1, h2, h3, q0, q1);
    mma16816(accD, h0, h1, h2, h3, q2, q3);
    mma16816(accC, l0, l1, l2, l3, p0, p1);
    mma16816(accD, l0, l1, l2, l3, p2, p3);
  }

  const int cA = n0g + nb + 2 * (lane & 3);
  const int cB = cA + 8;
  const float biA0 = b_ih[cA] + b_hh[cA], biA1 = b_ih[cA + 1] + b_hh[cA + 1];
  const float biB0 = b_ih[cB] + b_hh[cB], biB1 = b_ih[cB + 1] + b_hh[cB + 1];
  const int r0 = m0v + mrow + (lane >> 2);
#pragma unroll
  for (int mt = 0; mt < 2; mt++) {
    const float* aN = mt ? accC : accA;
    const float* aB2 = mt ? accD : accB;
    const int rr = r0 + mt * 16;
    if (rr < VV) {
      *(float2*)(g_table + (size_t)rr * G4 + cA) = make_float2(aN[0] + biA0, aN[1] + biA1);
      *(float2*)(g_table + (size_t)rr * G4 + cB) = make_float2(aB2[0] + biB0, aB2[1] + biB1);
    }
    if (rr + 8 < VV) {
      *(float2*)(g_table + (size_t)(rr + 8) * G4 + cA) = make_float2(aN[2] + biA0, aN[3] + biA1);
      *(float2*)(g_table + (size_t)(rr + 8) * G4 + cB) = make_float2(aB2[2] + biB0, aB2[3] + biB1);
    }
  }
}

// ---------------------------------------------------------------------------
// split h0 into transposed packed bf16x2 hi/lo
// ---------------------------------------------------------------------------
__global__ void split_h0_kernel(const float* __restrict__ h0) {
  const int i = blockIdx.x * 256 + threadIdx.x;   // 0..32767
  const int kp = i >> 7, b = i & 127;
  const float v0 = h0[(size_t)b * HH + 2 * kp];
  const float v1 = h0[(size_t)b * HH + 2 * kp + 1];
  const __nv_bfloat16 h0b = __float2bfloat16(v0), h1b = __float2bfloat16(v1);
  const __nv_bfloat16 l0b = __float2bfloat16(v0 - __bfloat162float(h0b));
  const __nv_bfloat16 l1b = __float2bfloat16(v1 - __bfloat162float(h1b));
  g_hThi[0][kp * 128 + b] =
      (uint32_t)*(const unsigned short*)&h0b | ((uint32_t)*(const unsigned short*)&h1b << 16);
  g_hTlo[0][kp * 128 + b] =
      (uint32_t)*(const unsigned short*)&l0b | ((uint32_t)*(const unsigned short*)&l1b << 16);
}

// ---------------------------------------------------------------------------
// persistent LSTM: 128 CTAs x 256 threads. Warp = (mh, kh): M16 x N64 x K128.
// A fragments loaded DIRECTLY from transposed global h -> no STS/LDSM/staging.
// ---------------------------------------------------------------------------
__global__ __launch_bounds__(256, 1) void lstm_mma_kernel(
    const int* __restrict__ x, const float* __restrict__ W_hh,
    const float* __restrict__ c0, float* __restrict__ out) {
  extern __shared__ __align__(16) char smem[];
  __nv_bfloat16* sb = (__nv_bfloat16*)smem;
  float* gsb = (float*)(smem + OFF_GSB_BYTES);   // [4][32][64] fp32
  __shared__ int tok[BBLK];

  const int blk = blockIdx.x;
  const int jg = blk & (NJG - 1);
  const int bg = blk >> 5;
  const int b0 = bg * BBLK;
  const int j0 = jg * JBLK;
  const int tid = threadIdx.x;
  const int w = tid >> 5, lane = tid & 31;

  // W split -> SMEM (row c = gate col 0..63, contiguous K, stride 520)
  for (int i = tid; i < 64 * HH; i += 256) {
    const int c = i >> 9, k = i & 511;
    const int g = ((c >> 4) << 9) + j0 + (c & 15);
    const float wv = W_hh[(size_t)g * HH + k];
    const __nv_bfloat16 whi = __float2bfloat16(wv);
    const __nv_bfloat16 wlo = __float2bfloat16(wv - __bfloat162float(whi));
    sb[OFF_WHI + c * WSTR + k] = whi;
    sb[OFF_WLO + c * WSTR + k] = wlo;
  }

  const int lb0 = tid >> 4,         jj0 = tid & 15;   // lb0 0..15
  const int lb1 = lb0 + 16;
  float cst0 = c0[(size_t)(b0 + lb0) * HH + j0 + jj0];
  float cst1 = c0[(size_t)(b0 + lb1) * HH + j0 + jj0];

  // warp tile: mh = batch 16-half, kh = K-quarter (128 elems = 64 kpairs)
  const int mh = w & 1, kh = w >> 1;
  const int mrow = mh << 4;
  const int sel = lane >> 3, li = lane & 7;
  const uint32_t smem0 = smem_u32(sb);

  // W fragment smem addrs: 4 n16 tiles
  uint32_t aWhi[4], aWlo[4];
#pragma unroll
  for (int nt = 0; nt < 4; nt++) {
    const int bo = (nt * 16 + li + ((sel >> 1) << 3)) * WSTR + (kh << 7) + ((sel & 1) << 3);
    aWhi[nt] = smem0 + (uint32_t)(OFF_WHI + bo) * 2;
    aWlo[nt] = smem0 + (uint32_t)(OFF_WLO + bo) * 2;
  }

  // A fragment global base: kpair = kh*64 + ku*8 + (lane&3); row = b0+mrow+(lane>>2)
  const int afrag_base = (kh * 64 + (lane & 3)) * 128 + b0 + mrow + (lane >> 2);

  // epilogue pair-store index (even jj threads store packed u32)
  const int kp_out = (j0 + jj0) >> 1;

  __syncthreads();   // W staged

  for (int t = 0; t < TT; t++) {
    const int rb = t & 1, wb = rb ^ 1;
    if (tid < BBLK) tok[tid] = __ldg(x + (size_t)(b0 + tid) * TT + t);

    const uint32_t* hTh = &g_hThi[rb][0];
    const uint32_t* hTl = &g_hTlo[rb][0];

    // ---- direct A-fragment loads: all 8 ku, hi+lo (64 LDG.32, max MLP) ----
    uint32_t ah[8][4], al[8][4];
#pragma unroll
    for (int ku = 0; ku < 8; ku++) {
      const int base = afrag_base + ku * 8 * 128;
      ah[ku][0] = ldcg_u32(hTh + base);
      ah[ku][1] = ldcg_u32(hTh + base + 8);
      ah[ku][2] = ldcg_u32(hTh + base + 4 * 128);
      ah[ku][3] = ldcg_u32(hTh + base + 4 * 128 + 8);
      al[ku][0] = ldcg_u32(hTl + base);
      al[ku][1] = ldcg_u32(hTl + base + 8);
      al[ku][2] = ldcg_u32(hTl + base + 4 * 128);
      al[ku][3] = ldcg_u32(hTl + base + 4 * 128 + 8);
    }

    // gx prefetch (hidden under MMA loop)
    const float* trow0 = g_table + (size_t)tok[lb0] * G4 + j0 + jj0;
    const float* trow1 = g_table + (size_t)tok[lb1] * G4 + j0 + jj0;
    const float gx0i = __ldg(trow0), gx0f = __ldg(trow0 + 512);
    const float gx0g = __ldg(trow0 + 1024), gx0o = __ldg(trow0 + 1536);
    const float gx1i = __ldg(trow1), gx1f = __ldg(trow1 + 512);
    const float gx1g = __ldg(trow1 + 1024), gx1o = __ldg(trow1 + 1536);

    float acc[8][4];
#pragma unroll
    for (int n = 0; n < 8; n++)
#pragma unroll
      for (int e = 0; e < 4; e++) acc[n][e] = 0.f;

#pragma unroll
    for (int ku = 0; ku < 8; ku++) {
      const uint32_t kb = (uint32_t)ku * 32;
#pragma unroll
      for (int nt = 0; nt < 4; nt++) {
        uint32_t p0, p1, p2, p3, q0, q1, q2, q3;
        ldsm4(p0, p1, p2, p3, aWhi[nt] + kb);
        ldsm4(q0, q1, q2, q3, aWlo[nt] + kb);
        mma16816(acc[2 * nt], ah[ku][0], ah[ku][1], ah[ku][2], ah[ku][3], p0, p1);
        mma16816(acc[2 * nt + 1], ah[ku][0], ah[ku][1], ah[ku][2], ah[ku][3], p2, p3);
        mma16816(acc[2 * nt], ah[ku][0], ah[ku][1], ah[ku][2], ah[ku][3], q0, q1);
        mma16816(acc[2 * nt + 1], ah[ku][0], ah[ku][1], ah[ku][2], ah[ku][3], q2, q3);
        mma16816(acc[2 * nt], al[ku][0], al[ku][1], al[ku][2], al[ku][3], p0, p1);
        mma16816(acc[2 * nt + 1], al[ku][0], al[ku][1], al[ku][2], al[ku][3], p2, p3);
      }
    }

    // partials -> gsb[kh][mrow..+16][64]
    {
      float* gk = gsb + kh * 2048;
      const int g = lane >> 2, tg2 = (lane & 3) * 2;
#pragma unroll
      for (int n = 0; n < 8; n++) {
        const int col = n * 8 + tg2;
        *(float2*)(gk + (mrow + g) * 64 + col) = make_float2(acc[n][0], acc[n][1]);
        *(float2*)(gk + (mrow + 8 + g) * 64 + col) = make_float2(acc[n][2], acc[n][3]);
      }
    }
    __syncthreads();

    // activations: 2 (b,j) pairs per thread; sum 4 K-partials
    float hn0, hn1;
    {
      const int r0 = lb0 * 64;
      const float gi = gsb[r0 + jj0] + gsb[2048 + r0 + jj0] + gsb[4096 + r0 + jj0] + gsb[6144 + r0 + jj0] + gx0i;
      const float gf = gsb[r0 + 16 + jj0] + gsb[2048 + r0 + 16 + jj0] + gsb[4096 + r0 + 16 + jj0] + gsb[6144 + r0 + 16 + jj0] + gx0f;
      const float gg = gsb[r0 + 32 + jj0] + gsb[2048 + r0 + 32 + jj0] + gsb[4096 + r0 + 32 + jj0] + gsb[6144 + r0 + 32 + jj0] + gx0g;
      const float go = gsb[r0 + 48 + jj0] + gsb[2048 + r0 + 48 + jj0] + gsb[4096 + r0 + 48 + jj0] + gsb[6144 + r0 + 48 + jj0] + gx0o;
      const float ii = fsig(gi), ff = fsig(gf), gc = ftanh(gg), oo = fsig(go);
      cst0 = ff * cst0 + ii * gc;
      hn0 = oo * ftanh(cst0);
    }
    {
      const int r1 = lb1 * 64;
      const float gi = gsb[r1 + jj0] + gsb[2048 + r1 + jj0] + gsb[4096 + r1 + jj0] + gsb[6144 + r1 + jj0] + gx1i;
      const float gf = gsb[r1 + 16 + jj0] + gsb[2048 + r1 + 16 + jj0] + gsb[4096 + r1 + 16 + jj0] + gsb[6144 + r1 + 16 + jj0] + gx1f;
      const float gg = gsb[r1 + 32 + jj0] + gsb[2048 + r1 + 32 + jj0] + gsb[4096 + r1 + 32 + jj0] + gsb[6144 + r1 + 32 + jj0] + gx1g;
      const float go = gsb[r1 + 48 + jj0] + gsb[2048 + r1 + 48 + jj0] + gsb[4096 + r1 + 48 + jj0] + gsb[6144 + r1 + 48 + jj0] + gx1o;
      const float ii = fsig(gi), ff = fsig(gf), gc = ftanh(gg), oo = fsig(go);
      cst1 = ff * cst1 + ii * gc;
      hn1 = oo * ftanh(cst1);
    }

    // split + pair with jj^1 neighbor (lane^1) + packed store to transposed h
    {
      const __nv_bfloat16 h0b = __float2bfloat16(hn0);
      const __nv_bfloat16 l0b = __float2bfloat16(hn0 - __bfloat162float(h0b));
      const __nv_bfloat16 h1b = __float2bfloat16(hn1);
      const __nv_bfloat16 l1b = __float2bfloat16(hn1 - __bfloat162float(h1b));
      const uint32_t hb0 = *(const unsigned short*)&h0b;
      const uint32_t lo0 = *(const unsigned short*)&l0b;
      const uint32_t hb1 = *(const unsigned short*)&h1b;
      const uint32_t lo1 = *(const unsigned short*)&l1b;
      const uint32_t phb0 = __shfl_xor_sync(0xffffffffu, hb0, 1);
      const uint32_t plo0 = __shfl_xor_sync(0xffffffffu, lo0, 1);
      const uint32_t phb1 = __shfl_xor_sync(0xffffffffu, hb1, 1);
      const uint32_t plo1 = __shfl_xor_sync(0xffffffffu, lo1, 1);
      if ((jj0 & 1) == 0) {
        stcg_u32(&g_hThi[wb][kp_out * 128 + b0 + lb0], hb0 | (phb0 << 16));
        stcg_u32(&g_hTlo[wb][kp_out * 128 + b0 + lb0], lo0 | (plo0 << 16));
        stcg_u32(&g_hThi[wb][kp_out * 128 + b0 + lb1], hb1 | (phb1 << 16));
        stcg_u32(&g_hTlo[wb][kp_out * 128 + b0 + lb1], lo1 | (plo1 << 16));
      }
      if (t == TT - 1) {
        const size_t i0 = (size_t)(b0 + lb0) * HH + j0 + jj0;
        const size_t i1 = (size_t)(b0 + lb1) * HH + j0 + jj0;
        out[128 + i0] = hn0; out[128 + 65536 + i0] = cst0;
        out[128 + i1] = hn1; out[128 + 65536 + i1] = cst1;
      }
    }

    // CTA-level barrier (proven pattern)
    if (t < TT - 1) {
      __syncthreads();
      if (tid == 0) {
        asm volatile("red.add.release.gpu.global.u32 [%0], %1;"
                     :: "l"(&g_bar[bg]), "r"(1u) : "memory");
        const unsigned tgt = (unsigned)(t + 1) * (unsigned)NJG;
        unsigned v;
        do {
          asm volatile("ld.acquire.gpu.global.u32 %0, [%1];"
                       : "=r"(v) : "l"(&g_bar[bg]) : "memory");
        } while (v < tgt);
      }
      __syncthreads();
    }
  }
}

// ---------------------------------------------------------------------------
__global__ void y_kernel(const float* __restrict__ fc_w,
                         const float* __restrict__ fc_b, float* __restrict__ out) {
  const int b = blockIdx.x;
  const int tid = threadIdx.x;
  const float* hr = out + 128 + (size_t)b * HH;
  float s = 0.f;
  for (int k = tid; k < HH; k += 128) s += hr[k] * fc_w[k];
#pragma unroll
  for (int o = 16; o; o >>= 1) s += __shfl_down_sync(0xffffffffu, s, o);
  __shared__ float red[4];
  if ((tid & 31) == 0) red[tid >> 5] = s;
  __syncthreads();
  if (tid == 0) out[b] = red[0] + red[1] + red[2] + red[3] + fc_b[0];
}

// ---------------------------------------------------------------------------
extern "C" void kernel_launch(void* const* d_in, const int* in_sizes, int n_in,
                              void* d_out, int out_size) {
  const int*   x    = (const int*)d_in[0];
  const float* h0   = (const float*)d_in[1];
  const float* c0   = (const float*)d_in[2];
  const float* emb  = (const float*)d_in[3];
  const float* W_ih = (const float*)d_in[4];
  const float* W_hh = (const float*)d_in[5];
  const float* b_ih = (const float*)d_in[6];
  const float* b_hh = (const float*)d_in[7];
  const float* fc_w = (const float*)d_in[8];
  const float* fc_b = (const float*)d_in[9];
  float* out = (float*)d_out;

  cudaFuncSetAttribute(lstm_mma_kernel, cudaFuncAttributeMaxDynamicSharedMemorySize,
                       SMEM_BYTES);
  cudaFuncSetAttribute(table_mma_kernel, cudaFuncAttributeMaxDynamicSharedMemorySize,
                       T_SMEM_BYTES);

  void* bar_p = nullptr;
  cudaGetSymbolAddress(&bar_p, g_bar);
  cudaMemsetAsync(bar_p, 0, sizeof(unsigned) * 8);                              // 0

  conv_split_all_kernel<<<((VV + G4) * 76 + 255) / 256, 256>>>(emb, W_ih);      // 1
  table_mma_kernel<<<dim3(G4 / 64, (VV + 63) / 64), 256, T_SMEM_BYTES>>>(b_ih, b_hh); // 2
  split_h0_kernel<<<128, 256>>>(h0);                                            // 3
  lstm_mma_kernel<<<128, 256, SMEM_BYTES>>>(x, W_hh, c0, out);                  // 4
  y_kernel<<<BB, 128>>>(fc_w, fc_b, out);                                       // 5
}

// round 13
// speedup vs baseline: 1.2706x; 1.2706x over previous
#include <cuda_runtime.h>
#include <cuda_bf16.h>
#include <cuda_fp16.h>
#include <cstdint>
#include <math.h>

#define VV 25000
#define EE 300
#define KP 304
#define HH 512
#define G4 2048
#define BB 128
#define TT 512
#define NBG 4
#define NJG 32
#define BBLK 32
#define JBLK 16

// ---------------- device scratch ----------------
__device__ float g_table[(size_t)VV * G4];        // ~205 MB
__device__ __half g_hf[2][BB * HH];               // fp16 h exchange (single!)
__device__ __nv_bfloat16 g_ehi[(size_t)VV * KP];
__device__ __nv_bfloat16 g_elo[(size_t)VV * KP];
__device__ __nv_bfloat16 g_whi[(size_t)G4 * KP];
__device__ __nv_bfloat16 g_wlo[(size_t)G4 * KP];
__device__ unsigned g_bar[8];

// LSTM SMEM (fp16-element offsets; stride 520)
#define WSTR 520
#define OFF_WHI 0
#define OFF_WLO (64 * WSTR)          // 33280
#define OFF_A   (2 * 64 * WSTR)      // 66560 (32 rows)
#define OFF_GSB_BYTES ((2 * 64 * WSTR + 32 * WSTR) * 2)  // 166400
#define SMEM_BYTES (OFF_GSB_BYTES + 4 * 32 * 64 * 4)     // 199168

// table GEMM SMEM (stride 312)
#define TSTR 312
#define T_AHI 0
#define T_ALO (64 * TSTR)
#define T_BHI (2 * 64 * TSTR)
#define T_BLO (3 * 64 * TSTR)
#define T_SMEM_BYTES (4 * 64 * TSTR * 2)

// ---------------- helpers ----------------
__device__ __forceinline__ uint32_t smem_u32(const void* p) {
  uint32_t a;
  asm("{ .reg .u64 t; cvta.to.shared.u64 t, %1; cvt.u32.u64 %0, t; }" : "=r"(a) : "l"(p));
  return a;
}
__device__ __forceinline__ void ldsm4(uint32_t& r0, uint32_t& r1, uint32_t& r2,
                                      uint32_t& r3, uint32_t addr) {
  asm volatile("ldmatrix.sync.aligned.m8n8.x4.shared.b16 {%0,%1,%2,%3}, [%4];"
               : "=r"(r0), "=r"(r1), "=r"(r2), "=r"(r3) : "r"(addr));
}
__device__ __forceinline__ void mma16816(float* c, uint32_t a0, uint32_t a1,
                                         uint32_t a2, uint32_t a3, uint32_t b0,
                                         uint32_t b1) {
  asm volatile(
      "mma.sync.aligned.m16n8k16.row.col.f32.bf16.bf16.f32 "
      "{%0,%1,%2,%3},{%4,%5,%6,%7},{%8,%9},{%0,%1,%2,%3};"
      : "+f"(c[0]), "+f"(c[1]), "+f"(c[2]), "+f"(c[3])
      : "r"(a0), "r"(a1), "r"(a2), "r"(a3), "r"(b0), "r"(b1));
}
__device__ __forceinline__ void mma16816h(float* c, uint32_t a0, uint32_t a1,
                                          uint32_t a2, uint32_t a3, uint32_t b0,
                                          uint32_t b1) {
  asm volatile(
      "mma.sync.aligned.m16n8k16.row.col.f32.f16.f16.f32 "
      "{%0,%1,%2,%3},{%4,%5,%6,%7},{%8,%9},{%0,%1,%2,%3};"
      : "+f"(c[0]), "+f"(c[1]), "+f"(c[2]), "+f"(c[3])
      : "r"(a0), "r"(a1), "r"(a2), "r"(a3), "r"(b0), "r"(b1));
}
__device__ __forceinline__ void stcg_f16(__half* p, __half v) {
  unsigned short u = *reinterpret_cast<unsigned short*>(&v);
  asm volatile("st.global.cg.u16 [%0], %1;" :: "l"(p), "h"(u) : "memory");
}
__device__ __forceinline__ float fsig(float x) { return __fdividef(1.f, 1.f + __expf(-x)); }
__device__ __forceinline__ float ftanh(float x) {
  return __fdividef(2.f, 1.f + __expf(-2.f * x)) - 1.f;
}

// ---------------------------------------------------------------------------
// fused split of emb (VV rows) and W_ih (G4 rows) -> bf16 hi/lo padded KP=304
// ---------------------------------------------------------------------------
__global__ void conv_split_all_kernel(const float* __restrict__ emb,
                                      const float* __restrict__ W_ih) {
  const int idx = blockIdx.x * 256 + threadIdx.x;
  if (idx >= (VV + G4) * 76) return;
  const int r = idx / 76, q = idx - r * 76;
  const float* src;
  __nv_bfloat16 *hi, *lo;
  if (r < VV) {
    src = emb + (size_t)r * EE;
    hi = g_ehi + (size_t)r * KP;
    lo = g_elo + (size_t)r * KP;
  } else {
    const int rr = r - VV;
    src = W_ih + (size_t)rr * EE;
    hi = g_whi + (size_t)rr * KP;
    lo = g_wlo + (size_t)rr * KP;
  }
  float4 v = make_float4(0.f, 0.f, 0.f, 0.f);
  if (q < 75) v = *(const float4*)(src + q * 4);
  const float vv[4] = {v.x, v.y, v.z, v.w};
  __nv_bfloat16 hb[4], lb[4];
#pragma unroll
  for (int i = 0; i < 4; i++) {
    hb[i] = __float2bfloat16(vv[i]);
    lb[i] = __float2bfloat16(vv[i] - __bfloat162float(hb[i]));
  }
  *(uint2*)(hi + q * 4) = *(uint2*)hb;
  *(uint2*)(lo + q * 4) = *(uint2*)lb;
}

// ---------------------------------------------------------------------------
// table GEMM (bf16-split HMMA): table[v][g] = emb[v].W_ih[g] + bias
// ---------------------------------------------------------------------------
__global__ __launch_bounds__(256, 1) void table_mma_kernel(
    const float* __restrict__ b_ih, const float* __restrict__ b_hh) {
  extern __shared__ __align__(16) char smem[];
  __nv_bfloat16* sb = (__nv_bfloat16*)smem;
  const int m0v = blockIdx.y * 64;
  const int n0g = blockIdx.x * 64;
  const int tid = threadIdx.x;
  const int w = tid >> 5, lane = tid & 31;

  for (int i = tid; i < 2432; i += 256) {
    const int r = i / 38, u = i - r * 38;
    const int v = m0v + r;
    uint4 hv = make_uint4(0, 0, 0, 0), lv = hv;
    if (v < VV) {
      hv = *(const uint4*)(g_ehi + (size_t)v * KP + u * 8);
      lv = *(const uint4*)(g_elo + (size_t)v * KP + u * 8);
    }
    *(uint4*)(sb + T_AHI + r * TSTR + u * 8) = hv;
    *(uint4*)(sb + T_ALO + r * TSTR + u * 8) = lv;
    const int g = n0g + r;
    *(uint4*)(sb + T_BHI + r * TSTR + u * 8) =
        *(const uint4*)(g_whi + (size_t)g * KP + u * 8);
    *(uint4*)(sb + T_BLO + r * TSTR + u * 8) =
        *(const uint4*)(g_wlo + (size_t)g * KP + u * 8);
  }
  __syncthreads();

  const int mrow = (w & 1) << 5;
  const int nb = (w >> 1) << 4;
  const int sel = lane >> 3, li = lane & 7;
  const uint32_t s0 = smem_u32(sb);
  const int aoff0 = (mrow + li + ((sel & 1) << 3)) * TSTR + ((sel >> 1) << 3);
  const int aoff1 = aoff0 + 16 * TSTR;
  const int boff = (nb + li + ((sel >> 1) << 3)) * TSTR + ((sel & 1) << 3);
  const uint32_t aAhi0 = s0 + (uint32_t)(T_AHI + aoff0) * 2;
  const uint32_t aAhi1 = s0 + (uint32_t)(T_AHI + aoff1) * 2;
  const uint32_t aAlo0 = s0 + (uint32_t)(T_ALO + aoff0) * 2;
  const uint32_t aAlo1 = s0 + (uint32_t)(T_ALO + aoff1) * 2;
  const uint32_t aBhi = s0 + (uint32_t)(T_BHI + boff) * 2;
  const uint32_t aBlo = s0 + (uint32_t)(T_BLO + boff) * 2;

  float accA[4] = {0, 0, 0, 0}, accB[4] = {0, 0, 0, 0};
  float accC[4] = {0, 0, 0, 0}, accD[4] = {0, 0, 0, 0};
#pragma unroll
  for (int ks = 0; ks < 19; ks++) {
    const uint32_t kb = (uint32_t)ks * 32;
    uint32_t h0, h1, h2, h3, l0, l1, l2, l3, p0, p1, p2, p3, q0, q1, q2, q3;
    ldsm4(p0, p1, p2, p3, aBhi + kb);
    ldsm4(q0, q1, q2, q3, aBlo + kb);
    ldsm4(h0, h1, h2, h3, aAhi0 + kb);
    ldsm4(l0, l1, l2, l3, aAlo0 + kb);
    mma16816(accA, h0, h1, h2, h3, p0, p1);
    mma16816(accB, h0, h1, h2, h3, p2, p3);
    mma16816(accA, h0, h1, h2, h3, q0, q1);
    mma16816(accB, h0, h1, h2, h3, q2, q3);
    mma16816(accA, l0, l1, l2, l3, p0, p1);
    mma16816(accB, l0, l1, l2, l3, p2, p3);
    ldsm4(h0, h1, h2, h3, aAhi1 + kb);
    ldsm4(l0, l1, l2, l3, aAlo1 + kb);
    mma16816(accC, h0, h1, h2, h3, p0, p1);
    mma16816(accD, h0, h1, h2, h3, p2, p3);
    mma16816(accC, h0, h1, h2, h3, q0, q1);
    mma16816(accD, h0, h1, h2, h3, q2, q3);
    mma16816(accC, l0, l1, l2, l3, p0, p1);
    mma16816(accD, l0, l1, l2, l3, p2, p3);
  }

  const int cA = n0g + nb + 2 * (lane & 3);
  const int cB = cA + 8;
  const float biA0 = b_ih[cA] + b_hh[cA], biA1 = b_ih[cA + 1] + b_hh[cA + 1];
  const float biB0 = b_ih[cB] + b_hh[cB], biB1 = b_ih[cB + 1] + b_hh[cB + 1];
  const int r0 = m0v + mrow + (lane >> 2);
#pragma unroll
  for (int mt = 0; mt < 2; mt++) {
    const float* aN = mt ? accC : accA;
    const float* aB2 = mt ? accD : accB;
    const int rr = r0 + mt * 16;
    if (rr < VV) {
      *(float2*)(g_table + (size_t)rr * G4 + cA) = make_float2(aN[0] + biA0, aN[1] + biA1);
      *(float2*)(g_table + (size_t)rr * G4 + cB) = make_float2(aB2[0] + biB0, aB2[1] + biB1);
    }
    if (rr + 8 < VV) {
      *(float2*)(g_table + (size_t)(rr + 8) * G4 + cA) = make_float2(aN[2] + biA0, aN[3] + biA1);
      *(float2*)(g_table + (size_t)(rr + 8) * G4 + cB) = make_float2(aB2[2] + biB0, aB2[3] + biB1);
    }
  }
}

// ---------------------------------------------------------------------------
__global__ void split_h0_kernel(const float* __restrict__ h0) {
  const int i = blockIdx.x * 256 + threadIdx.x;
  g_hf[0][i] = __float2half(h0[i]);
}

// ---------------------------------------------------------------------------
// persistent LSTM: 128 CTAs x 256 threads. Warp = (ng, kh): M32 x N32 x K128.
// fp16 A (no split) x fp16 W-split (lo scaled x1024, separate accumulator):
// 2 MMA passes instead of 3. W_hi hoisted to registers; W_lo via ldsm.
// ---------------------------------------------------------------------------
__global__ __launch_bounds__(256, 1) void lstm_mma_kernel(
    const int* __restrict__ x, const float* __restrict__ W_hh,
    const float* __restrict__ c0, float* __restrict__ out) {
  extern __shared__ __align__(16) char smem[];
  __half* sb = (__half*)smem;
  float* gsb = (float*)(smem + OFF_GSB_BYTES);   // [4][32][64] fp32 (separate)
  __shared__ int tok[BBLK];

  const int blk = blockIdx.x;
  const int jg = blk & (NJG - 1);
  const int bg = blk >> 5;
  const int b0 = bg * BBLK;
  const int j0 = jg * JBLK;
  const int tid = threadIdx.x;
  const int w = tid >> 5, lane = tid & 31;

  // W split -> SMEM (row c = gate col 0..63, contiguous K, stride 520)
  for (int i = tid; i < 64 * HH; i += 256) {
    const int c = i >> 9, k = i & 511;
    const int g = ((c >> 4) << 9) + j0 + (c & 15);
    const float wv = W_hh[(size_t)g * HH + k];
    const __half whi = __float2half(wv);
    const __half wlo = __float2half((wv - __half2float(whi)) * 1024.0f);
    sb[OFF_WHI + c * WSTR + k] = whi;
    sb[OFF_WLO + c * WSTR + k] = wlo;
  }

  const int lb0 = tid >> 4,         jj0 = tid & 15;
  const int lb1 = (tid + 256) >> 4, jj1 = (tid + 256) & 15;
  float cst0 = c0[(size_t)(b0 + lb0) * HH + j0 + jj0];
  float cst1 = c0[(size_t)(b0 + lb1) * HH + j0 + jj1];

  // warp tile: ng = N-half (32 cols), kh = K-quarter (128 elems)
  const int ng = w & 1, kh = w >> 1;
  const int nb = ng << 5;
  const int kbase = kh << 7;
  const int sel = lane >> 3, li = lane & 7;
  const uint32_t smem0 = smem_u32(sb);

  uint32_t aA[2];
#pragma unroll
  for (int m = 0; m < 2; m++) {
    const int ao = (m * 16 + li + ((sel & 1) << 3)) * WSTR + kbase + ((sel >> 1) << 3);
    aA[m] = smem0 + (uint32_t)(OFF_A + ao) * 2;
  }
  uint32_t aWhi[2], aWlo[2];
#pragma unroll
  for (int nt = 0; nt < 2; nt++) {
    const int bo = (nb + nt * 16 + li + ((sel >> 1) << 3)) * WSTR + kbase + ((sel & 1) << 3);
    aWhi[nt] = smem0 + (uint32_t)(OFF_WHI + bo) * 2;
    aWlo[nt] = smem0 + (uint32_t)(OFF_WLO + bo) * 2;
  }

  __syncthreads();   // W staged

  // preload W_hi fragments into registers (loop-invariant, 64 regs)
  uint32_t wp[2][8][4];
#pragma unroll
  for (int nt = 0; nt < 2; nt++)
#pragma unroll
    for (int ku = 0; ku < 8; ku++)
      ldsm4(wp[nt][ku][0], wp[nt][ku][1], wp[nt][ku][2], wp[nt][ku][3],
            aWhi[nt] + (uint32_t)ku * 32);

  for (int t = 0; t < TT; t++) {
    const int rb = t & 1, wb = rb ^ 1;
    if (tid < BBLK) tok[tid] = __ldg(x + (size_t)(b0 + tid) * TT + t);

    // load A (32 rows x 512 fp16 = 32 KB) into padded SMEM
    {
      const uint4* srcF = (const uint4*)(g_hf[rb] + (size_t)b0 * HH);
#pragma unroll
      for (int it = 0; it < 8; it++) {
        const int i = tid + it * 256;
        const int r = i >> 6, u = i & 63;
        *(uint4*)(sb + OFF_A + r * WSTR + u * 8) = __ldcg(srcF + r * 64 + u);
      }
    }
    __syncthreads();

    // gx prefetch (hidden under MMA loop)
    const float* trow0 = g_table + (size_t)tok[lb0] * G4 + j0 + jj0;
    const float* trow1 = g_table + (size_t)tok[lb1] * G4 + j0 + jj1;
    const float gx0i = __ldg(trow0), gx0f = __ldg(trow0 + 512);
    const float gx0g = __ldg(trow0 + 1024), gx0o = __ldg(trow0 + 1536);
    const float gx1i = __ldg(trow1), gx1f = __ldg(trow1 + 512);
    const float gx1g = __ldg(trow1 + 1024), gx1o = __ldg(trow1 + 1536);

    float acc1[2][4][4], acc2[2][4][4];
#pragma unroll
    for (int m = 0; m < 2; m++)
#pragma unroll
      for (int n = 0; n < 4; n++)
#pragma unroll
        for (int e = 0; e < 4; e++) { acc1[m][n][e] = 0.f; acc2[m][n][e] = 0.f; }

#pragma unroll
    for (int ku = 0; ku < 8; ku++) {
      const uint32_t kb = (uint32_t)ku * 32;
      uint32_t a0[4], a1[4], q0[4], q1[4];
      ldsm4(a0[0], a0[1], a0[2], a0[3], aA[0] + kb);
      ldsm4(a1[0], a1[1], a1[2], a1[3], aA[1] + kb);
      ldsm4(q0[0], q0[1], q0[2], q0[3], aWlo[0] + kb);
      ldsm4(q1[0], q1[1], q1[2], q1[3], aWlo[1] + kb);
      // A * W_hi
      mma16816h(acc1[0][0], a0[0], a0[1], a0[2], a0[3], wp[0][ku][0], wp[0][ku][1]);
      mma16816h(acc1[0][1], a0[0], a0[1], a0[2], a0[3], wp[0][ku][2], wp[0][ku][3]);
      mma16816h(acc1[0][2], a0[0], a0[1], a0[2], a0[3], wp[1][ku][0], wp[1][ku][1]);
      mma16816h(acc1[0][3], a0[0], a0[1], a0[2], a0[3], wp[1][ku][2], wp[1][ku][3]);
      mma16816h(acc1[1][0], a1[0], a1[1], a1[2], a1[3], wp[0][ku][0], wp[0][ku][1]);
      mma16816h(acc1[1][1], a1[0], a1[1], a1[2], a1[3], wp[0][ku][2], wp[0][ku][3]);
      mma16816h(acc1[1][2], a1[0], a1[1], a1[2], a1[3], wp[1][ku][0], wp[1][ku][1]);
      mma16816h(acc1[1][3], a1[0], a1[1], a1[2], a1[3], wp[1][ku][2], wp[1][ku][3]);
      // A * W_lo_scaled (separate accumulator)
      mma16816h(acc2[0][0], a0[0], a0[1], a0[2], a0[3], q0[0], q0[1]);
      mma16816h(acc2[0][1], a0[0], a0[1], a0[2], a0[3], q0[2], q0[3]);
      mma16816h(acc2[0][2], a0[0], a0[1], a0[2], a0[3], q1[0], q1[1]);
      mma16816h(acc2[0][3], a0[0], a0[1], a0[2], a0[3], q1[2], q1[3]);
      mma16816h(acc2[1][0], a1[0], a1[1], a1[2], a1[3], q0[0], q0[1]);
      mma16816h(acc2[1][1], a1[0], a1[1], a1[2], a1[3], q0[2], q0[3]);
      mma16816h(acc2[1][2], a1[0], a1[1], a1[2], a1[3], q1[0], q1[1]);
      mma16816h(acc2[1][3], a1[0], a1[1], a1[2], a1[3], q1[2], q1[3]);
    }

    // partials -> gsb[kh][row][col], combining lo-accumulator (x 1/1024)
    {
      float* gk = gsb + kh * 2048;
      const int g = lane >> 2, tg2 = (lane & 3) * 2;
      const float s = 0.0009765625f;
#pragma unroll
      for (int m = 0; m < 2; m++)
#pragma unroll
        for (int n = 0; n < 4; n++) {
          const int col = nb + n * 8 + tg2;
          *(float2*)(gk + (m * 16 + g) * 64 + col) =
              make_float2(fmaf(acc2[m][n][0], s, acc1[m][n][0]),
                          fmaf(acc2[m][n][1], s, acc1[m][n][1]));
          *(float2*)(gk + (m * 16 + 8 + g) * 64 + col) =
              make_float2(fmaf(acc2[m][n][2], s, acc1[m][n][2]),
                          fmaf(acc2[m][n][3], s, acc1[m][n][3]));
        }
    }
    __syncthreads();

    // activations: 2 (b,j) pairs per thread; sum 4 K-partials
    {
      const int r0 = lb0 * 64;
      const float gi = gsb[r0 + jj0] + gsb[2048 + r0 + jj0] + gsb[4096 + r0 + jj0] + gsb[6144 + r0 + jj0] + gx0i;
      const float gf = gsb[r0 + 16 + jj0] + gsb[2048 + r0 + 16 + jj0] + gsb[4096 + r0 + 16 + jj0] + gsb[6144 + r0 + 16 + jj0] + gx0f;
      const float gg = gsb[r0 + 32 + jj0] + gsb[2048 + r0 + 32 + jj0] + gsb[4096 + r0 + 32 + jj0] + gsb[6144 + r0 + 32 + jj0] + gx0g;
      const float go = gsb[r0 + 48 + jj0] + gsb[2048 + r0 + 48 + jj0] + gsb[4096 + r0 + 48 + jj0] + gsb[6144 + r0 + 48 + jj0] + gx0o;
      const float ii = fsig(gi), ff = fsig(gf), gc = ftanh(gg), oo = fsig(go);
      cst0 = ff * cst0 + ii * gc;
      const float hn = oo * ftanh(cst0);
      const size_t idx = (size_t)(b0 + lb0) * HH + j0 + jj0;
      stcg_f16(&g_hf[wb][idx], __float2half(hn));
      if (t == TT - 1) { out[128 + idx] = hn; out[128 + 65536 + idx] = cst0; }
    }
    {
      const int r1 = lb1 * 64;
      const float gi = gsb[r1 + jj1] + gsb[2048 + r1 + jj1] + gsb[4096 + r1 + jj1] + gsb[6144 + r1 + jj1] + gx1i;
      const float gf = gsb[r1 + 16 + jj1] + gsb[2048 + r1 + 16 + jj1] + gsb[4096 + r1 + 16 + jj1] + gsb[6144 + r1 + 16 + jj1] + gx1f;
      const float gg = gsb[r1 + 32 + jj1] + gsb[2048 + r1 + 32 + jj1] + gsb[4096 + r1 + 32 + jj1] + gsb[6144 + r1 + 32 + jj1] + gx1g;
      const float go = gsb[r1 + 48 + jj1] + gsb[2048 + r1 + 48 + jj1] + gsb[4096 + r1 + 48 + jj1] + gsb[6144 + r1 + 48 + jj1] + gx1o;
      const float ii = fsig(gi), ff = fsig(gf), gc = ftanh(gg), oo = fsig(go);
      cst1 = ff * cst1 + ii * gc;
      const float hn = oo * ftanh(cst1);
      const size_t idx = (size_t)(b0 + lb1) * HH + j0 + jj1;
      stcg_f16(&g_hf[wb][idx], __float2half(hn));
      if (t == TT - 1) { out[128 + idx] = hn; out[128 + 65536 + idx] = cst1; }
    }

    // CTA-level barrier (proven pattern)
    if (t < TT - 1) {
      __syncthreads();
      if (tid == 0) {
        asm volatile("red.add.release.gpu.global.u32 [%0], %1;"
                     :: "l"(&g_bar[bg]), "r"(1u) : "memory");
        const unsigned tgt = (unsigned)(t + 1) * (unsigned)NJG;
        unsigned v;
        do {
          asm volatile("ld.acquire.gpu.global.u32 %0, [%1];"
                       : "=r"(v) : "l"(&g_bar[bg]) : "memory");
        } while (v < tgt);
      }
      __syncthreads();
    }
  }
}

// ---------------------------------------------------------------------------
__global__ void y_kernel(const float* __restrict__ fc_w,
                         const float* __restrict__ fc_b, float* __restrict__ out) {
  const int b = blockIdx.x;
  const int tid = threadIdx.x;
  const float* hr = out + 128 + (size_t)b * HH;
  float s = 0.f;
  for (int k = tid; k < HH; k += 128) s += hr[k] * fc_w[k];
#pragma unroll
  for (int o = 16; o; o >>= 1) s += __shfl_down_sync(0xffffffffu, s, o);
  __shared__ float red[4];
  if ((tid & 31) == 0) red[tid >> 5] = s;
  __syncthreads();
  if (tid == 0) out[b] = red[0] + red[1] + red[2] + red[3] + fc_b[0];
}

// ---------------------------------------------------------------------------
extern "C" void kernel_launch(void* const* d_in, const int* in_sizes, int n_in,
                              void* d_out, int out_size) {
  const int*   x    = (const int*)d_in[0];
  const float* h0   = (const float*)d_in[1];
  const float* c0   = (const float*)d_in[2];
  const float* emb  = (const float*)d_in[3];
  const float* W_ih = (const float*)d_in[4];
  const float* W_hh = (const float*)d_in[5];
  const float* b_ih = (const float*)d_in[6];
  const float* b_hh = (const float*)d_in[7];
  const float* fc_w = (const float*)d_in[8];
  const float* fc_b = (const float*)d_in[9];
  float* out = (float*)d_out;

  cudaFuncSetAttribute(lstm_mma_kernel, cudaFuncAttributeMaxDynamicSharedMemorySize,
                       SMEM_BYTES);
  cudaFuncSetAttribute(table_mma_kernel, cudaFuncAttributeMaxDynamicSharedMemorySize,
                       T_SMEM_BYTES);

  void* bar_p = nullptr;
  cudaGetSymbolAddress(&bar_p, g_bar);
  cudaMemsetAsync(bar_p, 0, sizeof(unsigned) * 8);                              // 0

  conv_split_all_kernel<<<((VV + G4) * 76 + 255) / 256, 256>>>(emb, W_ih);      // 1
  table_mma_kernel<<<dim3(G4 / 64, (VV + 63) / 64), 256, T_SMEM_BYTES>>>(b_ih, b_hh); // 2
  split_h0_kernel<<<256, 256>>>(h0);                                            // 3
  lstm_mma_kernel<<<128, 256, SMEM_BYTES>>>(x, W_hh, c0, out);                  // 4
  y_kernel<<<BB, 128>>>(fc_w, fc_b, out);                                       // 5
}

// round 14
// speedup vs baseline: 1.4038x; 1.1048x over previous
#include <cuda_runtime.h>
#include <cuda_bf16.h>
#include <cuda_fp16.h>
#include <cstdint>
#include <math.h>

#define VV 25000
#define EE 300
#define KP 304
#define HH 512
#define G4 2048
#define BB 128
#define TT 512
#define NBG 4
#define NJG 32
#define BBLK 32
#define JBLK 16

// ---------------- device scratch ----------------
__device__ float g_table[(size_t)VV * G4];        // ~205 MB
__device__ __half g_hf[2][BB * HH];               // fp16 h exchange
__device__ __nv_bfloat16 g_ehi[(size_t)VV * KP];
__device__ __nv_bfloat16 g_elo[(size_t)VV * KP];
__device__ __nv_bfloat16 g_whi[(size_t)G4 * KP];
__device__ __nv_bfloat16 g_wlo[(size_t)G4 * KP];
__device__ unsigned g_bar[8];

// LSTM SMEM (fp16-element offsets; stride 520): W_hi + A + gsb
#define WSTR 520
#define OFF_WHI 0
#define OFF_A   (64 * WSTR)                          // 33280
#define OFF_GSB_BYTES ((64 * WSTR + 32 * WSTR) * 2)  // 99840
#define SMEM_BYTES (OFF_GSB_BYTES + 4 * 32 * 64 * 4) // 132608

// table GEMM SMEM (stride 312)
#define TSTR 312
#define T_AHI 0
#define T_ALO (64 * TSTR)
#define T_BHI (2 * 64 * TSTR)
#define T_BLO (3 * 64 * TSTR)
#define T_SMEM_BYTES (4 * 64 * TSTR * 2)

// ---------------- helpers ----------------
__device__ __forceinline__ uint32_t smem_u32(const void* p) {
  uint32_t a;
  asm("{ .reg .u64 t; cvta.to.shared.u64 t, %1; cvt.u32.u64 %0, t; }" : "=r"(a) : "l"(p));
  return a;
}
__device__ __forceinline__ void ldsm4(uint32_t& r0, uint32_t& r1, uint32_t& r2,
                                      uint32_t& r3, uint32_t addr) {
  asm volatile("ldmatrix.sync.aligned.m8n8.x4.shared.b16 {%0,%1,%2,%3}, [%4];"
               : "=r"(r0), "=r"(r1), "=r"(r2), "=r"(r3) : "r"(addr));
}
__device__ __forceinline__ void mma16816(float* c, uint32_t a0, uint32_t a1,
                                         uint32_t a2, uint32_t a3, uint32_t b0,
                                         uint32_t b1) {
  asm volatile(
      "mma.sync.aligned.m16n8k16.row.col.f32.bf16.bf16.f32 "
      "{%0,%1,%2,%3},{%4,%5,%6,%7},{%8,%9},{%0,%1,%2,%3};"
      : "+f"(c[0]), "+f"(c[1]), "+f"(c[2]), "+f"(c[3])
      : "r"(a0), "r"(a1), "r"(a2), "r"(a3), "r"(b0), "r"(b1));
}
__device__ __forceinline__ void mma16816h(float* c, uint32_t a0, uint32_t a1,
                                          uint32_t a2, uint32_t a3, uint32_t b0,
                                          uint32_t b1) {
  asm volatile(
      "mma.sync.aligned.m16n8k16.row.col.f32.f16.f16.f32 "
      "{%0,%1,%2,%3},{%4,%5,%6,%7},{%8,%9},{%0,%1,%2,%3};"
      : "+f"(c[0]), "+f"(c[1]), "+f"(c[2]), "+f"(c[3])
      : "r"(a0), "r"(a1), "r"(a2), "r"(a3), "r"(b0), "r"(b1));
}
__device__ __forceinline__ void stcg_f16(__half* p, __half v) {
  unsigned short u = *reinterpret_cast<unsigned short*>(&v);
  asm volatile("st.global.cg.u16 [%0], %1;" :: "l"(p), "h"(u) : "memory");
}
__device__ __forceinline__ float fsig(float x) { return __fdividef(1.f, 1.f + __expf(-x)); }
__device__ __forceinline__ float ftanh(float x) {
  return __fdividef(2.f, 1.f + __expf(-2.f * x)) - 1.f;
}

// ---------------------------------------------------------------------------
// fused split of emb (VV rows) and W_ih (G4 rows) -> bf16 hi/lo padded KP=304
// ---------------------------------------------------------------------------
__global__ void conv_split_all_kernel(const float* __restrict__ emb,
                                      const float* __restrict__ W_ih) {
  const int idx = blockIdx.x * 256 + threadIdx.x;
  if (idx >= (VV + G4) * 76) return;
  const int r = idx / 76, q = idx - r * 76;
  const float* src;
  __nv_bfloat16 *hi, *lo;
  if (r < VV) {
    src = emb + (size_t)r * EE;
    hi = g_ehi + (size_t)r * KP;
    lo = g_elo + (size_t)r * KP;
  } else {
    const int rr = r - VV;
    src = W_ih + (size_t)rr * EE;
    hi = g_whi + (size_t)rr * KP;
    lo = g_wlo + (size_t)rr * KP;
  }
  float4 v = make_float4(0.f, 0.f, 0.f, 0.f);
  if (q < 75) v = *(const float4*)(src + q * 4);
  const float vv[4] = {v.x, v.y, v.z, v.w};
  __nv_bfloat16 hb[4], lb[4];
#pragma unroll
  for (int i = 0; i < 4; i++) {
    hb[i] = __float2bfloat16(vv[i]);
    lb[i] = __float2bfloat16(vv[i] - __bfloat162float(hb[i]));
  }
  *(uint2*)(hi + q * 4) = *(uint2*)hb;
  *(uint2*)(lo + q * 4) = *(uint2*)lb;
}

// ---------------------------------------------------------------------------
// table GEMM (bf16-split HMMA): table[v][g] = emb[v].W_ih[g] + bias
// ---------------------------------------------------------------------------
__global__ __launch_bounds__(256, 1) void table_mma_kernel(
    const float* __restrict__ b_ih, const float* __restrict__ b_hh) {
  extern __shared__ __align__(16) char smem[];
  __nv_bfloat16* sb = (__nv_bfloat16*)smem;
  const int m0v = blockIdx.y * 64;
  const int n0g = blockIdx.x * 64;
  const int tid = threadIdx.x;
  const int w = tid >> 5, lane = tid & 31;

  for (int i = tid; i < 2432; i += 256) {
    const int r = i / 38, u = i - r * 38;
    const int v = m0v + r;
    uint4 hv = make_uint4(0, 0, 0, 0), lv = hv;
    if (v < VV) {
      hv = *(const uint4*)(g_ehi + (size_t)v * KP + u * 8);
      lv = *(const uint4*)(g_elo + (size_t)v * KP + u * 8);
    }
    *(uint4*)(sb + T_AHI + r * TSTR + u * 8) = hv;
    *(uint4*)(sb + T_ALO + r * TSTR + u * 8) = lv;
    const int g = n0g + r;
    *(uint4*)(sb + T_BHI + r * TSTR + u * 8) =
        *(const uint4*)(g_whi + (size_t)g * KP + u * 8);
    *(uint4*)(sb + T_BLO + r * TSTR + u * 8) =
        *(const uint4*)(g_wlo + (size_t)g * KP + u * 8);
  }
  __syncthreads();

  const int mrow = (w & 1) << 5;
  const int nb = (w >> 1) << 4;
  const int sel = lane >> 3, li = lane & 7;
  const uint32_t s0 = smem_u32(sb);
  const int aoff0 = (mrow + li + ((sel & 1) << 3)) * TSTR + ((sel >> 1) << 3);
  const int aoff1 = aoff0 + 16 * TSTR;
  const int boff = (nb + li + ((sel >> 1) << 3)) * TSTR + ((sel & 1) << 3);
  const uint32_t aAhi0 = s0 + (uint32_t)(T_AHI + aoff0) * 2;
  const uint32_t aAhi1 = s0 + (uint32_t)(T_AHI + aoff1) * 2;
  const uint32_t aAlo0 = s0 + (uint32_t)(T_ALO + aoff0) * 2;
  const uint32_t aAlo1 = s0 + (uint32_t)(T_ALO + aoff1) * 2;
  const uint32_t aBhi = s0 + (uint32_t)(T_BHI + boff) * 2;
  const uint32_t aBlo = s0 + (uint32_t)(T_BLO + boff) * 2;

  float accA[4] = {0, 0, 0, 0}, accB[4] = {0, 0, 0, 0};
  float accC[4] = {0, 0, 0, 0}, accD[4] = {0, 0, 0, 0};
#pragma unroll
  for (int ks = 0; ks < 19; ks++) {
    const uint32_t kb = (uint32_t)ks * 32;
    uint32_t h0, h1, h2, h3, l0, l1, l2, l3, p0, p1, p2, p3, q0, q1, q2, q3;
    ldsm4(p0, p1, p2, p3, aBhi + kb);
    ldsm4(q0, q1, q2, q3, aBlo + kb);
    ldsm4(h0, h1, h2, h3, aAhi0 + kb);
    ldsm4(l0, l1, l2, l3, aAlo0 + kb);
    mma16816(accA, h0, h1, h2, h3, p0, p1);
    mma16816(accB, h0, h1, h2, h3, p2, p3);
    mma16816(accA, h0, h1, h2, h3, q0, q1);
    mma16816(accB, h0, h1, h2, h3, q2, q3);
    mma16816(accA, l0, l1, l2, l3, p0, p1);
    mma16816(accB, l0, l1, l2, l3, p2, p3);
    ldsm4(h0, h1, h2, h3, aAhi1 + kb);
    ldsm4(l0, l1, l2, l3, aAlo1 + kb);
    mma16816(accC, h0, h1, h2, h3, p0, p1);
    mma16816(accD, h0, h1, h2, h3, p2, p3);
    mma16816(accC, h0, h1, h2, h3, q0, q1);
    mma16816(accD, h0, h1, h2, h3, q2, q3);
    mma16816(accC, l0, l1, l2, l3, p0, p1);
    mma16816(accD, l0, l1, l2, l3, p2, p3);
  }

  const int cA = n0g + nb + 2 * (lane & 3);
  const int cB = cA + 8;
  const float biA0 = b_ih[cA] + b_hh[cA], biA1 = b_ih[cA + 1] + b_hh[cA + 1];
  const float biB0 = b_ih[cB] + b_hh[cB], biB1 = b_ih[cB + 1] + b_hh[cB + 1];
  const int r0 = m0v + mrow + (lane >> 2);
#pragma unroll
  for (int mt = 0; mt < 2; mt++) {
    const float* aN = mt ? accC : accA;
    const float* aB2 = mt ? accD : accB;
    const int rr = r0 + mt * 16;
    if (rr < VV) {
      *(float2*)(g_table + (size_t)rr * G4 + cA) = make_float2(aN[0] + biA0, aN[1] + biA1);
      *(float2*)(g_table + (size_t)rr * G4 + cB) = make_float2(aB2[0] + biB0, aB2[1] + biB1);
    }
    if (rr + 8 < VV) {
      *(float2*)(g_table + (size_t)(rr + 8) * G4 + cA) = make_float2(aN[2] + biA0, aN[3] + biA1);
      *(float2*)(g_table + (size_t)(rr + 8) * G4 + cB) = make_float2(aB2[2] + biB0, aB2[3] + biB1);
    }
  }
}

// ---------------------------------------------------------------------------
__global__ void split_h0_kernel(const float* __restrict__ h0) {
  const int i = blockIdx.x * 256 + threadIdx.x;
  g_hf[0][i] = __float2half(h0[i]);
}

// ---------------------------------------------------------------------------
// persistent LSTM: 128 CTAs x 256 threads. Warp = (ng, kh): M32 x N32 x K128.
// SINGLE-pass pure fp16 MMA (W error 2^-11, calibrated safe). W_hi in regs;
// inner loop per ku: 2 A-ldsm4 + 16 MMA.
// ---------------------------------------------------------------------------
__global__ __launch_bounds__(256, 1) void lstm_mma_kernel(
    const int* __restrict__ x, const float* __restrict__ W_hh,
    const float* __restrict__ c0, float* __restrict__ out) {
  extern __shared__ __align__(16) char smem[];
  __half* sb = (__half*)smem;
  float* gsb = (float*)(smem + OFF_GSB_BYTES);   // [4][32][64] fp32
  __shared__ int tok[BBLK];

  const int blk = blockIdx.x;
  const int jg = blk & (NJG - 1);
  const int bg = blk >> 5;
  const int b0 = bg * BBLK;
  const int j0 = jg * JBLK;
  const int tid = threadIdx.x;
  const int w = tid >> 5, lane = tid & 31;

  // W -> SMEM fp16 (row c = gate col 0..63, contiguous K, stride 520)
  for (int i = tid; i < 64 * HH; i += 256) {
    const int c = i >> 9, k = i & 511;
    const int g = ((c >> 4) << 9) + j0 + (c & 15);
    sb[OFF_WHI + c * WSTR + k] = __float2half(W_hh[(size_t)g * HH + k]);
  }

  const int lb0 = tid >> 4,         jj0 = tid & 15;
  const int lb1 = (tid + 256) >> 4, jj1 = (tid + 256) & 15;
  float cst0 = c0[(size_t)(b0 + lb0) * HH + j0 + jj0];
  float cst1 = c0[(size_t)(b0 + lb1) * HH + j0 + jj1];

  // warp tile: ng = N-half (32 cols), kh = K-quarter (128 elems)
  const int ng = w & 1, kh = w >> 1;
  const int nb = ng << 5;
  const int kbase = kh << 7;
  const int sel = lane >> 3, li = lane & 7;
  const uint32_t smem0 = smem_u32(sb);

  uint32_t aA[2];
#pragma unroll
  for (int m = 0; m < 2; m++) {
    const int ao = (m * 16 + li + ((sel & 1) << 3)) * WSTR + kbase + ((sel >> 1) << 3);
    aA[m] = smem0 + (uint32_t)(OFF_A + ao) * 2;
  }
  uint32_t aWhi[2];
#pragma unroll
  for (int nt = 0; nt < 2; nt++) {
    const int bo = (nb + nt * 16 + li + ((sel >> 1) << 3)) * WSTR + kbase + ((sel & 1) << 3);
    aWhi[nt] = smem0 + (uint32_t)(OFF_WHI + bo) * 2;
  }

  __syncthreads();   // W staged

  // preload W fragments into registers (loop-invariant, 64 regs)
  uint32_t wp[2][8][4];
#pragma unroll
  for (int nt = 0; nt < 2; nt++)
#pragma unroll
    for (int ku = 0; ku < 8; ku++)
      ldsm4(wp[nt][ku][0], wp[nt][ku][1], wp[nt][ku][2], wp[nt][ku][3],
            aWhi[nt] + (uint32_t)ku * 32);

  for (int t = 0; t < TT; t++) {
    const int rb = t & 1, wb = rb ^ 1;
    if (tid < BBLK) tok[tid] = __ldg(x + (size_t)(b0 + tid) * TT + t);

    // load A (32 rows x 512 fp16 = 32 KB) into padded SMEM
    {
      const uint4* srcF = (const uint4*)(g_hf[rb] + (size_t)b0 * HH);
#pragma unroll
      for (int it = 0; it < 8; it++) {
        const int i = tid + it * 256;
        const int r = i >> 6, u = i & 63;
        *(uint4*)(sb + OFF_A + r * WSTR + u * 8) = __ldcg(srcF + r * 64 + u);
      }
    }
    __syncthreads();

    // gx prefetch (hidden under MMA loop)
    const float* trow0 = g_table + (size_t)tok[lb0] * G4 + j0 + jj0;
    const float* trow1 = g_table + (size_t)tok[lb1] * G4 + j0 + jj1;
    const float gx0i = __ldg(trow0), gx0f = __ldg(trow0 + 512);
    const float gx0g = __ldg(trow0 + 1024), gx0o = __ldg(trow0 + 1536);
    const float gx1i = __ldg(trow1), gx1f = __ldg(trow1 + 512);
    const float gx1g = __ldg(trow1 + 1024), gx1o = __ldg(trow1 + 1536);

    float acc[2][4][4];
#pragma unroll
    for (int m = 0; m < 2; m++)
#pragma unroll
      for (int n = 0; n < 4; n++)
#pragma unroll
        for (int e = 0; e < 4; e++) acc[m][n][e] = 0.f;

#pragma unroll
    for (int ku = 0; ku < 8; ku++) {
      const uint32_t kb = (uint32_t)ku * 32;
      uint32_t a0[4], a1[4];
      ldsm4(a0[0], a0[1], a0[2], a0[3], aA[0] + kb);
      ldsm4(a1[0], a1[1], a1[2], a1[3], aA[1] + kb);
      mma16816h(acc[0][0], a0[0], a0[1], a0[2], a0[3], wp[0][ku][0], wp[0][ku][1]);
      mma16816h(acc[0][1], a0[0], a0[1], a0[2], a0[3], wp[0][ku][2], wp[0][ku][3]);
      mma16816h(acc[0][2], a0[0], a0[1], a0[2], a0[3], wp[1][ku][0], wp[1][ku][1]);
      mma16816h(acc[0][3], a0[0], a0[1], a0[2], a0[3], wp[1][ku][2], wp[1][ku][3]);
      mma16816h(acc[1][0], a1[0], a1[1], a1[2], a1[3], wp[0][ku][0], wp[0][ku][1]);
      mma16816h(acc[1][1], a1[0], a1[1], a1[2], a1[3], wp[0][ku][2], wp[0][ku][3]);
      mma16816h(acc[1][2], a1[0], a1[1], a1[2], a1[3], wp[1][ku][0], wp[1][ku][1]);
      mma16816h(acc[1][3], a1[0], a1[1], a1[2], a1[3], wp[1][ku][2], wp[1][ku][3]);
    }

    // partials -> gsb[kh][row][col]
    {
      float* gk = gsb + kh * 2048;
      const int g = lane >> 2, tg2 = (lane & 3) * 2;
#pragma unroll
      for (int m = 0; m < 2; m++)
#pragma unroll
        for (int n = 0; n < 4; n++) {
          const int col = nb + n * 8 + tg2;
          *(float2*)(gk + (m * 16 + g) * 64 + col) =
              make_float2(acc[m][n][0], acc[m][n][1]);
          *(float2*)(gk + (m * 16 + 8 + g) * 64 + col) =
              make_float2(acc[m][n][2], acc[m][n][3]);
        }
    }
    __syncthreads();

    // activations: 2 (b,j) pairs per thread; sum 4 K-partials
    {
      const int r0 = lb0 * 64;
      const float gi = gsb[r0 + jj0] + gsb[2048 + r0 + jj0] + gsb[4096 + r0 + jj0] + gsb[6144 + r0 + jj0] + gx0i;
      const float gf = gsb[r0 + 16 + jj0] + gsb[2048 + r0 + 16 + jj0] + gsb[4096 + r0 + 16 + jj0] + gsb[6144 + r0 + 16 + jj0] + gx0f;
      const float gg = gsb[r0 + 32 + jj0] + gsb[2048 + r0 + 32 + jj0] + gsb[4096 + r0 + 32 + jj0] + gsb[6144 + r0 + 32 + jj0] + gx0g;
      const float go = gsb[r0 + 48 + jj0] + gsb[2048 + r0 + 48 + jj0] + gsb[4096 + r0 + 48 + jj0] + gsb[6144 + r0 + 48 + jj0] + gx0o;
      const float ii = fsig(gi), ff = fsig(gf), gc = ftanh(gg), oo = fsig(go);
      cst0 = ff * cst0 + ii * gc;
      const float hn = oo * ftanh(cst0);
      const size_t idx = (size_t)(b0 + lb0) * HH + j0 + jj0;
      stcg_f16(&g_hf[wb][idx], __float2half(hn));
      if (t == TT - 1) { out[128 + idx] = hn; out[128 + 65536 + idx] = cst0; }
    }
    {
      const int r1 = lb1 * 64;
      const float gi = gsb[r1 + jj1] + gsb[2048 + r1 + jj1] + gsb[4096 + r1 + jj1] + gsb[6144 + r1 + jj1] + gx1i;
      const float gf = gsb[r1 + 16 + jj1] + gsb[2048 + r1 + 16 + jj1] + gsb[4096 + r1 + 16 + jj1] + gsb[6144 + r1 + 16 + jj1] + gx1f;
      const float gg = gsb[r1 + 32 + jj1] + gsb[2048 + r1 + 32 + jj1] + gsb[4096 + r1 + 32 + jj1] + gsb[6144 + r1 + 32 + jj1] + gx1g;
      const float go = gsb[r1 + 48 + jj1] + gsb[2048 + r1 + 48 + jj1] + gsb[4096 + r1 + 48 + jj1] + gsb[6144 + r1 + 48 + jj1] + gx1o;
      const float ii = fsig(gi), ff = fsig(gf), gc = ftanh(gg), oo = fsig(go);
      cst1 = ff * cst1 + ii * gc;
      const float hn = oo * ftanh(cst1);
      const size_t idx = (size_t)(b0 + lb1) * HH + j0 + jj1;
      stcg_f16(&g_hf[wb][idx], __float2half(hn));
      if (t == TT - 1) { out[128 + idx] = hn; out[128 + 65536 + idx] = cst1; }
    }

    // CTA-level barrier (proven pattern)
    if (t < TT - 1) {
      __syncthreads();
      if (tid == 0) {
        asm volatile("red.add.release.gpu.global.u32 [%0], %1;"
                     :: "l"(&g_bar[bg]), "r"(1u) : "memory");
        const unsigned tgt = (unsigned)(t + 1) * (unsigned)NJG;
        unsigned v;
        do {
          asm volatile("ld.acquire.gpu.global.u32 %0, [%1];"
                       : "=r"(v) : "l"(&g_bar[bg]) : "memory");
        } while (v < tgt);
      }
      __syncthreads();
    }
  }
}

// ---------------------------------------------------------------------------
__global__ void y_kernel(const float* __restrict__ fc_w,
                         const float* __restrict__ fc_b, float* __restrict__ out) {
  const int b = blockIdx.x;
  const int tid = threadIdx.x;
  const float* hr = out + 128 + (size_t)b * HH;
  float s = 0.f;
  for (int k = tid; k < HH; k += 128) s += hr[k] * fc_w[k];
#pragma unroll
  for (int o = 16; o; o >>= 1) s += __shfl_down_sync(0xffffffffu, s, o);
  __shared__ float red[4];
  if ((tid & 31) == 0) red[tid >> 5] = s;
  __syncthreads();
  if (tid == 0) out[b] = red[0] + red[1] + red[2] + red[3] + fc_b[0];
}

// ---------------------------------------------------------------------------
extern "C" void kernel_launch(void* const* d_in, const int* in_sizes, int n_in,
                              void* d_out, int out_size) {
  const int*   x    = (const int*)d_in[0];
  const float* h0   = (const float*)d_in[1];
  const float* c0   = (const float*)d_in[2];
  const float* emb  = (const float*)d_in[3];
  const float* W_ih = (const float*)d_in[4];
  const float* W_hh = (const float*)d_in[5];
  const float* b_ih = (const float*)d_in[6];
  const float* b_hh = (const float*)d_in[7];
  const float* fc_w = (const float*)d_in[8];
  const float* fc_b = (const float*)d_in[9];
  float* out = (float*)d_out;

  cudaFuncSetAttribute(lstm_mma_kernel, cudaFuncAttributeMaxDynamicSharedMemorySize,
                       SMEM_BYTES);
  cudaFuncSetAttribute(table_mma_kernel, cudaFuncAttributeMaxDynamicSharedMemorySize,
                       T_SMEM_BYTES);

  void* bar_p = nullptr;
  cudaGetSymbolAddress(&bar_p, g_bar);
  cudaMemsetAsync(bar_p, 0, sizeof(unsigned) * 8);                              // 0

  conv_split_all_kernel<<<((VV + G4) * 76 + 255) / 256, 256>>>(emb, W_ih);      // 1
  table_mma_kernel<<<dim3(G4 / 64, (VV + 63) / 64), 256, T_SMEM_BYTES>>>(b_ih, b_hh); // 2
  split_h0_kernel<<<256, 256>>>(h0);                                            // 3
  lstm_mma_kernel<<<128, 256, SMEM_BYTES>>>(x, W_hh, c0, out);                  // 4
  y_kernel<<<BB, 128>>>(fc_w, fc_b, out);                                       // 5
}